// round 15
// baseline (speedup 1.0000x reference)
#include <cuda_runtime.h>

// Shapes: lx_in/ux_in (32768 rows x 1024 fp32), lc/uc (32768), x_min/x_max (1024).
// Outputs concatenated in d_out: [lx_out | ux_out | lc_out | uc_out].
//
// R13 per-thread structure (the wallclock champion: 128 threads/row, two
// float4 per thread per array, .cs streaming, redundant finalize) packed two
// rows per 256-thread block, with INDEPENDENT named barriers per 128-thread
// row group (bar.sync 1/2, 128). Barrier scope stays 4 warps (R13) while the
// grid halves to 16384 blocks (less churn than R13, no 8-warp coupling like
// the failed R7).

#define NROWS 32768
#define INNER 1024
#define NTHREADS 256
#define GROUP 128
#define GWARPS (GROUP / 32)   // 4
#define F4 (INNER / 4)        // 256 float4 per row

__device__ __forceinline__ void group_bar(int id) {
    asm volatile("bar.sync %0, %1;" :: "r"(id), "r"(GROUP) : "memory");
}

__global__ __launch_bounds__(NTHREADS)
void crown_relu_nb(const float* __restrict__ lx_in,
                   const float* __restrict__ ux_in,
                   const float* __restrict__ lc_in,
                   const float* __restrict__ uc_in,
                   const float* __restrict__ x_min,
                   const float* __restrict__ x_max,
                   float* __restrict__ lx_out,
                   float* __restrict__ ux_out,
                   float* __restrict__ lc_out,
                   float* __restrict__ uc_out)
{
    const int t  = threadIdx.x;
    const int g  = t >> 7;            // row group 0/1
    const int tt = t & (GROUP - 1);   // thread within group
    const int row = blockIdx.x * 2 + g;
    const long long base4 = (long long)row * F4;

    const float4* lx4 = reinterpret_cast<const float4*>(lx_in) + base4;
    const float4* ux4 = reinterpret_cast<const float4*>(ux_in) + base4;
    const float4* mn4 = reinterpret_cast<const float4*>(x_min);
    const float4* mx4 = reinterpret_cast<const float4*>(x_max);

    // Front-batched: 4 independent streaming LDG.128 per thread.
    float4 lv0 = __ldcs(lx4 + tt);
    float4 lv1 = __ldcs(lx4 + tt + GROUP);
    float4 uv0 = __ldcs(ux4 + tt);
    float4 uv1 = __ldcs(ux4 + tt + GROUP);

    // Hot 8KB tables via caching loads.
    float4 mn0 = __ldg(mn4 + tt);
    float4 mn1 = __ldg(mn4 + tt + GROUP);
    float4 mx0 = __ldg(mx4 + tt);
    float4 mx1 = __ldg(mx4 + tt + GROUP);

    // Hoisted scalar loads: latency overlaps the reduction/barrier below.
    const float lc = lc_in[row];
    const float uc = uc_in[row];

    // mask_lower*lx == min(lx*mn, lx*mx); mask_upper*ux == max(...).
    float sl = fminf(lv0.x * mn0.x, lv0.x * mx0.x)
             + fminf(lv0.y * mn0.y, lv0.y * mx0.y)
             + fminf(lv0.z * mn0.z, lv0.z * mx0.z)
             + fminf(lv0.w * mn0.w, lv0.w * mx0.w)
             + fminf(lv1.x * mn1.x, lv1.x * mx1.x)
             + fminf(lv1.y * mn1.y, lv1.y * mx1.y)
             + fminf(lv1.z * mn1.z, lv1.z * mx1.z)
             + fminf(lv1.w * mn1.w, lv1.w * mx1.w);
    float su = fmaxf(uv0.x * mn0.x, uv0.x * mx0.x)
             + fmaxf(uv0.y * mn0.y, uv0.y * mx0.y)
             + fmaxf(uv0.z * mn0.z, uv0.z * mx0.z)
             + fmaxf(uv0.w * mn0.w, uv0.w * mx0.w)
             + fmaxf(uv1.x * mn1.x, uv1.x * mx1.x)
             + fmaxf(uv1.y * mn1.y, uv1.y * mx1.y)
             + fmaxf(uv1.z * mn1.z, uv1.z * mx1.z)
             + fmaxf(uv1.w * mn1.w, uv1.w * mx1.w);

    #pragma unroll
    for (int o = 16; o > 0; o >>= 1) {
        sl += __shfl_xor_sync(0xffffffffu, sl, o);
        su += __shfl_xor_sync(0xffffffffu, su, o);
    }

    __shared__ float s_l[2][GWARPS];
    __shared__ float s_u[2][GWARPS];
    const int lane = t & 31;
    const int gw   = tt >> 5;   // warp within group
    if (lane == 0) { s_l[g][gw] = sl; s_u[g][gw] = su; }
    group_bar(g + 1);   // independent 4-warp barrier per row group

    // Every thread redundantly finalizes its own row.
    float l = lc, u = uc;
    #pragma unroll
    for (int w = 0; w < GWARPS; w++) { l += s_l[g][w]; u += s_u[g][w]; }

    const bool  alive = (l >= 0.0f);
    const bool  cross = (l < 0.0f) && (u > 0.0f);
    const float slope = cross ? fminf(fmaxf(u / (u - l), 0.0f), 1.0f) : 1.0f;

    const float fl = alive ? 1.0f : 0.0f;
    const float fu = alive ? 1.0f : (cross ? slope : 0.0f);

    if (tt == 0) {
        lc_out[row] = fl * lc;
        uc_out[row] = alive ? uc : (cross ? (slope * uc - slope * l) : 0.0f);
    }

    float4* lo4 = reinterpret_cast<float4*>(lx_out) + base4;
    float4* uo4 = reinterpret_cast<float4*>(ux_out) + base4;

    float4 a;
    a.x = fl * lv0.x; a.y = fl * lv0.y; a.z = fl * lv0.z; a.w = fl * lv0.w;
    __stcs(lo4 + tt, a);
    a.x = fl * lv1.x; a.y = fl * lv1.y; a.z = fl * lv1.z; a.w = fl * lv1.w;
    __stcs(lo4 + tt + GROUP, a);
    a.x = fu * uv0.x; a.y = fu * uv0.y; a.z = fu * uv0.z; a.w = fu * uv0.w;
    __stcs(uo4 + tt, a);
    a.x = fu * uv1.x; a.y = fu * uv1.y; a.z = fu * uv1.z; a.w = fu * uv1.w;
    __stcs(uo4 + tt + GROUP, a);
}

extern "C" void kernel_launch(void* const* d_in, const int* in_sizes, int n_in,
                              void* d_out, int out_size)
{
    const float* lx_in = (const float*)d_in[0];
    const float* ux_in = (const float*)d_in[1];
    const float* lc_in = (const float*)d_in[2];
    const float* uc_in = (const float*)d_in[3];
    const float* x_min = (const float*)d_in[4];
    const float* x_max = (const float*)d_in[5];

    float* out = (float*)d_out;
    const long long big = (long long)NROWS * INNER;   // 33,554,432
    float* lx_out = out;
    float* ux_out = out + big;
    float* lc_out = out + 2 * big;
    float* uc_out = out + 2 * big + NROWS;

    crown_relu_nb<<<NROWS / 2, NTHREADS>>>(lx_in, ux_in, lc_in, uc_in,
                                           x_min, x_max,
                                           lx_out, ux_out, lc_out, uc_out);
}

// round 16
// speedup vs baseline: 1.2108x; 1.2108x over previous
#include <cuda_runtime.h>

// Shapes: lx_in/ux_in (32768 rows x 1024 fp32), lc/uc (32768), x_min/x_max (1024).
// Outputs concatenated in d_out: [lx_out | ux_out | lc_out | uc_out].
//
// CHAMPION (R13, 82.4us wall / 80.3us ncu / 76% DRAM): 128 threads per
// row-block, two float4 per thread per array (4 bulk LDG.128 front-batched),
// 4-warp barrier, single __syncthreads, redundant per-thread finalize,
// .cs streaming hints both directions. Re-benched unchanged to confirm.

#define NROWS 32768
#define INNER 1024
#define NTHREADS 128
#define NWARPS (NTHREADS / 32)   // 4
#define F4 (INNER / 4)           // 256 float4 per row

__global__ __launch_bounds__(NTHREADS)
void crown_relu_128(const float* __restrict__ lx_in,
                    const float* __restrict__ ux_in,
                    const float* __restrict__ lc_in,
                    const float* __restrict__ uc_in,
                    const float* __restrict__ x_min,
                    const float* __restrict__ x_max,
                    float* __restrict__ lx_out,
                    float* __restrict__ ux_out,
                    float* __restrict__ lc_out,
                    float* __restrict__ uc_out)
{
    const int row = blockIdx.x;
    const int t   = threadIdx.x;
    const long long base4 = (long long)row * F4;

    const float4* lx4 = reinterpret_cast<const float4*>(lx_in) + base4;
    const float4* ux4 = reinterpret_cast<const float4*>(ux_in) + base4;
    const float4* mn4 = reinterpret_cast<const float4*>(x_min);
    const float4* mx4 = reinterpret_cast<const float4*>(x_max);

    // Front-batched: 4 independent streaming LDG.128 per thread.
    float4 lv0 = __ldcs(lx4 + t);
    float4 lv1 = __ldcs(lx4 + t + NTHREADS);
    float4 uv0 = __ldcs(ux4 + t);
    float4 uv1 = __ldcs(ux4 + t + NTHREADS);

    // Hot 8KB tables via caching loads.
    float4 mn0 = __ldg(mn4 + t);
    float4 mn1 = __ldg(mn4 + t + NTHREADS);
    float4 mx0 = __ldg(mx4 + t);
    float4 mx1 = __ldg(mx4 + t + NTHREADS);

    // Hoisted scalar loads: latency overlaps the reduction/barrier below.
    const float lc = lc_in[row];
    const float uc = uc_in[row];

    // mask_lower*lx == min(lx*mn, lx*mx); mask_upper*ux == max(...).
    float sl = fminf(lv0.x * mn0.x, lv0.x * mx0.x)
             + fminf(lv0.y * mn0.y, lv0.y * mx0.y)
             + fminf(lv0.z * mn0.z, lv0.z * mx0.z)
             + fminf(lv0.w * mn0.w, lv0.w * mx0.w)
             + fminf(lv1.x * mn1.x, lv1.x * mx1.x)
             + fminf(lv1.y * mn1.y, lv1.y * mx1.y)
             + fminf(lv1.z * mn1.z, lv1.z * mx1.z)
             + fminf(lv1.w * mn1.w, lv1.w * mx1.w);
    float su = fmaxf(uv0.x * mn0.x, uv0.x * mx0.x)
             + fmaxf(uv0.y * mn0.y, uv0.y * mx0.y)
             + fmaxf(uv0.z * mn0.z, uv0.z * mx0.z)
             + fmaxf(uv0.w * mn0.w, uv0.w * mx0.w)
             + fmaxf(uv1.x * mn1.x, uv1.x * mx1.x)
             + fmaxf(uv1.y * mn1.y, uv1.y * mx1.y)
             + fmaxf(uv1.z * mn1.z, uv1.z * mx1.z)
             + fmaxf(uv1.w * mn1.w, uv1.w * mx1.w);

    #pragma unroll
    for (int o = 16; o > 0; o >>= 1) {
        sl += __shfl_xor_sync(0xffffffffu, sl, o);
        su += __shfl_xor_sync(0xffffffffu, su, o);
    }

    __shared__ float s_l[NWARPS];
    __shared__ float s_u[NWARPS];
    const int lane = t & 31;
    const int wid  = t >> 5;
    if (lane == 0) { s_l[wid] = sl; s_u[wid] = su; }
    __syncthreads();   // the ONLY barrier (4 warps)

    // Every thread redundantly finalizes.
    float l = lc, u = uc;
    #pragma unroll
    for (int w = 0; w < NWARPS; w++) { l += s_l[w]; u += s_u[w]; }

    const bool  alive = (l >= 0.0f);
    const bool  cross = (l < 0.0f) && (u > 0.0f);
    const float slope = cross ? fminf(fmaxf(u / (u - l), 0.0f), 1.0f) : 1.0f;

    const float fl = alive ? 1.0f : 0.0f;
    const float fu = alive ? 1.0f : (cross ? slope : 0.0f);

    if (t == 0) {
        lc_out[row] = fl * lc;
        uc_out[row] = alive ? uc : (cross ? (slope * uc - slope * l) : 0.0f);
    }

    float4* lo4 = reinterpret_cast<float4*>(lx_out) + base4;
    float4* uo4 = reinterpret_cast<float4*>(ux_out) + base4;

    float4 a;
    a.x = fl * lv0.x; a.y = fl * lv0.y; a.z = fl * lv0.z; a.w = fl * lv0.w;
    __stcs(lo4 + t, a);
    a.x = fl * lv1.x; a.y = fl * lv1.y; a.z = fl * lv1.z; a.w = fl * lv1.w;
    __stcs(lo4 + t + NTHREADS, a);
    a.x = fu * uv0.x; a.y = fu * uv0.y; a.z = fu * uv0.z; a.w = fu * uv0.w;
    __stcs(uo4 + t, a);
    a.x = fu * uv1.x; a.y = fu * uv1.y; a.z = fu * uv1.z; a.w = fu * uv1.w;
    __stcs(uo4 + t + NTHREADS, a);
}

extern "C" void kernel_launch(void* const* d_in, const int* in_sizes, int n_in,
                              void* d_out, int out_size)
{
    const float* lx_in = (const float*)d_in[0];
    const float* ux_in = (const float*)d_in[1];
    const float* lc_in = (const float*)d_in[2];
    const float* uc_in = (const float*)d_in[3];
    const float* x_min = (const float*)d_in[4];
    const float* x_max = (const float*)d_in[5];

    float* out = (float*)d_out;
    const long long big = (long long)NROWS * INNER;   // 33,554,432
    float* lx_out = out;
    float* ux_out = out + big;
    float* lc_out = out + 2 * big;
    float* uc_out = out + 2 * big + NROWS;

    crown_relu_128<<<NROWS, NTHREADS>>>(lx_in, ux_in, lc_in, uc_in,
                                        x_min, x_max,
                                        lx_out, ux_out, lc_out, uc_out);
}